// round 8
// baseline (speedup 1.0000x reference)
#include <cuda_runtime.h>

#define B_      64
#define S_      200
#define DK_     32
#define NQ1     4097
#define GX      6
#define CHUNK   128
#define NCH_TOT 33            // ceil(4097/128)
#define TSTEPS  (S_ - 1)      // 199

// Persistent device state (no allocations allowed in kernel_launch).
static __device__ float g_h[(B_ * NQ1 + CHUNK) * DK_];   // h state + pad
static __device__ float g_ht[S_ * B_ * DK_];             // h_tilde per step
static __device__ float g_learn[S_ * B_ * DK_];          // all_learning [t][b][k]
static __device__ float g_it[S_ * B_ * DK_];             // it_emb      [t][b][k]
static __device__ int   g_flag[B_];                      // per-batch step counter

typedef unsigned long long ull;

__device__ __forceinline__ ull ffma2(ull a, ull b, ull c) {
    ull d;
    asm("fma.rn.f32x2 %0, %1, %2, %3;" : "=l"(d) : "l"(a), "l"(b), "l"(c));
    return d;
}
__device__ __forceinline__ ull fadd2(ull a, ull b) {
    ull d;
    asm("add.rn.f32x2 %0, %1, %2;" : "=l"(d) : "l"(a), "l"(b));
    return d;
}
__device__ __forceinline__ void upk2(ull v, float& lo, float& hi) {
    asm("mov.b64 {%0,%1}, %2;" : "=f"(lo), "=f"(hi) : "l"(v));
}
__device__ __forceinline__ unsigned smem_u32(const void* p) {
    unsigned a;
    asm("{ .reg .u64 t; cvta.to.shared.u64 t, %1; cvt.u32.u64 %0, t; }" : "=r"(a) : "l"(p));
    return a;
}
__device__ __forceinline__ void bulk_g2s(unsigned sdst, const void* gsrc, unsigned bytes,
                                         unsigned mbar) {
    asm volatile(
        "cp.async.bulk.shared::cta.global.mbarrier::complete_tx::bytes [%0], [%1], %2, [%3];"
        :: "r"(sdst), "l"(gsrc), "r"(bytes), "r"(mbar) : "memory");
}
__device__ __forceinline__ void mbar_wait(unsigned mbar, unsigned phase) {
    asm volatile(
        "{\n\t.reg .pred P;\n\t"
        "W_%=:\n\t"
        "mbarrier.try_wait.parity.shared.b64 P, [%0], %1, 0x989680;\n\t"
        "@P bra D_%=;\n\t"
        "bra.uni W_%=;\n\t"
        "D_%=:\n\t}"
        :: "r"(mbar), "r"(phase) : "memory");
}

// ---------------------------------------------------------------------------
// K1: init h, zero h_tilde buffers, zero flags, pred[:,0]=0
// ---------------------------------------------------------------------------
__global__ void k_init(const float* __restrict__ h0, float* __restrict__ pred) {
    int stride = gridDim.x * blockDim.x;
    int gid = blockIdx.x * blockDim.x + threadIdx.x;
    for (int i = gid; i < B_ * NQ1 * DK_; i += stride) {
        int nk = i % (NQ1 * DK_);
        g_h[i] = h0[nk];
    }
    for (int i = gid; i < S_ * B_ * DK_; i += stride) g_ht[i] = 0.0f;
    if (gid < B_) { pred[gid * S_] = 0.0f; g_flag[gid] = 0; }
}

// ---------------------------------------------------------------------------
// K2: precompute all_learning[t][b][k] and it_emb[t][b][k]
// ---------------------------------------------------------------------------
__global__ void k_embed(const int* __restrict__ e_data, const int* __restrict__ at_data,
                        const int* __restrict__ it_data, const float* __restrict__ a_data,
                        const float* __restrict__ E_e, const float* __restrict__ E_at,
                        const float* __restrict__ E_it,
                        const float* __restrict__ W1, const float* __restrict__ b1) {
    int idx = blockIdx.x * blockDim.x + threadIdx.x;
    if (idx >= S_ * B_ * DK_) return;
    int t = idx / (B_ * DK_);
    int rem = idx - t * (B_ * DK_);
    int b = rem >> 5;
    int k = rem & 31;

    int e  = e_data[b * S_ + t];
    int at = at_data[b * S_ + t];
    int it = it_data[b * S_ + t];
    float a = a_data[b * S_ + t];

    const float* ee  = E_e  + e  * DK_;
    const float* eat = E_at + at * DK_;
    const float* w1k = W1 + k * (3 * DK_);

    float s = b1[k];
    float ws = 0.0f;
#pragma unroll
    for (int j = 0; j < DK_; j++) {
        s = fmaf(ee[j],  w1k[j],        s);
        s = fmaf(eat[j], w1k[DK_ + j],  s);
        ws += w1k[2 * DK_ + j];
    }
    s = fmaf(a, ws, s);

    g_learn[(t * B_ + b) * DK_ + k] = s;
    g_it[(t * B_ + b) * DK_ + k]    = E_it[it * DK_ + k];
}

// ---------------------------------------------------------------------------
// K3: h_tilde0[b] = sum_n q[e_data[b,0], n] * h0[n,:]
// ---------------------------------------------------------------------------
__global__ void k_ht0(const int* __restrict__ e_data, const float* __restrict__ q,
                      const float* __restrict__ h0) {
    int b = blockIdx.x;
    int w = threadIdx.x >> 5;
    int lane = threadIdx.x & 31;
    const float* qr = q + (long)e_data[b * S_] * NQ1;
    float acc = 0.0f;
    for (int n = w; n < NQ1; n += 8) {
        float qv = qr[n];
        if (qv != 0.0f) acc = fmaf(qv, h0[n * DK_ + lane], acc);
    }
    atomicAdd(&g_ht[b * DK_ + lane], acc);
}

// ---------------------------------------------------------------------------
// k_seq: persistent kernel over all 199 steps. grid = (GX, 64), 256 thr, 3/SM.
//   128-row chunks staged by cp.async.bulk into a 2-slot ring. Warps free-run;
//   slot refill is issued by the LAST warp to finish the slot (smem counter
//   election — exactly one producer per use, no empty barrier, no blocking).
// ---------------------------------------------------------------------------
__global__ void __launch_bounds__(256, 3)
k_seq(const int* __restrict__ e_data, const float* __restrict__ q,
      const float* __restrict__ E_e,
      const float* __restrict__ W2, const float* __restrict__ b2,
      const float* __restrict__ W3, const float* __restrict__ b3,
      const float* __restrict__ W4, const float* __restrict__ b4,
      const float* __restrict__ W5, const float* __restrict__ b5,
      float* __restrict__ pred) {
    __shared__ __align__(16) float sh_h[2][CHUNK * DK_];   // 32 KB
    __shared__ __align__(16) float sh_qe[2][144];
    __shared__ __align__(16) float sh_qn[2][144];
    __shared__ __align__(8)  ull   sh_mbar[2];             // full0 full1
    __shared__ int   sh_cnt[2];                            // slot reader counters
    __shared__ float sh_x[4 * DK_];
    __shared__ float sh_LG[DK_];
    __shared__ float sh_c[DK_];
    __shared__ float sh_gl[DK_];
    __shared__ float sh_cB[DK_];

    const int b = blockIdx.y;
    const int bx = blockIdx.x;
    const int tid = threadIdx.x;
    const int w = tid >> 5;
    const int lane = tid & 31;

    const int cs = (bx * NCH_TOT) / GX;
    const int ce = ((bx + 1) * NCH_TOT) / GX;
    const int nch = ce - cs;                // 5 or 6 (>2 required by ring depth)
    const int rstart = cs * CHUNK;
    const int total_u = TSTEPS * nch;

    const unsigned mb_full = smem_u32(&sh_mbar[0]);

    if (tid == 0) {
#pragma unroll
        for (int s = 0; s < 2; s++) {
            asm volatile("mbarrier.init.shared.b64 [%0], 1;" :: "r"(mb_full + s * 8));
            sh_cnt[s] = 0;
        }
        asm volatile("fence.proxy.async.shared::cta;" ::: "memory");
    }
    __syncthreads();

#define ISSUE_U(U)                                                                      \
    {                                                                                   \
        int tu = (U) / nch;                                                             \
        int cu = (U) - tu * nch;                                                        \
        int rs = rstart + cu * CHUNK;                                                   \
        int slot_i = (U) & 1;                                                           \
        unsigned mb = mb_full + slot_i * 8;                                             \
        asm volatile("mbarrier.arrive.expect_tx.shared.b64 _, [%0], %1;"                \
                     :: "r"(mb), "r"(17440u) : "memory");                               \
        bulk_g2s(smem_u32(&sh_h[slot_i][0]), g_h + ((long)b * NQ1 + rs) * DK_,          \
                 16384u, mb);                                                           \
        int etu = e_data[b * S_ + tu];                                                  \
        int enu = e_data[b * S_ + tu + 1];                                              \
        const void* pe = (const void*)(((ull)(q + (long)etu * NQ1 + rs)) & ~15ULL);     \
        const void* pn = (const void*)(((ull)(q + (long)enu * NQ1 + rs)) & ~15ULL);     \
        bulk_g2s(smem_u32(&sh_qe[slot_i][0]), pe, 528u, mb);                            \
        bulk_g2s(smem_u32(&sh_qn[slot_i][0]), pn, 528u, mb);                            \
    }

    if (tid == 0) { ISSUE_U(0) ISSUE_U(1) }

    // W4h[lane, 0..31] as 16 f32x2 registers — loaded ONCE for all 199 steps.
    ull w2r[16];
    {
        const ulonglong2* wp = reinterpret_cast<const ulonglong2*>(W4 + lane * (3 * DK_));
#pragma unroll
        for (int i = 0; i < 8; i++) {
            ulonglong2 p = __ldg(wp + i);
            w2r[2 * i] = p.x;
            w2r[2 * i + 1] = p.y;
        }
    }

    for (int t = 0; t < TSTEPS; t++) {
        // ---- gate: all 6 blocks of batch b finished step t-1 ----
        if (t > 0) {
            if (tid == 0) {
                int need = 6 * t;
                int v;
                do {
                    asm volatile("ld.global.acquire.gpu.b32 %0, [%1];"
                                 : "=r"(v) : "l"(&g_flag[b]));
                    if (v >= need) break;
                    __nanosleep(64);
                } while (true);
            }
            __syncthreads();
        }

        const int e_t = e_data[b * S_ + t];
        const int qoe = e_t & 3;
        const int qon = e_data[b * S_ + t + 1] & 3;

        // ---- prologue: split across warps 0 (lg), 1 (gl), 2 (it-part of c) ----
        if (w < 3) {
            if (w == 0) {
                float x0 = (t == 0) ? 0.0f : g_learn[((t - 1) * B_ + b) * DK_ + lane];
                float x1 = g_it[(t * B_ + b) * DK_ + lane];
                float x2 = g_learn[(t * B_ + b) * DK_ + lane];
                float x3 = g_ht[(t * B_ + b) * DK_ + lane];
                sh_x[lane]           = x0;
                sh_x[DK_ + lane]     = x1;
                sh_x[2 * DK_ + lane] = x2;
                sh_x[3 * DK_ + lane] = x3;
            }
            asm volatile("bar.sync 7, 96;" ::: "memory");

            float lg = 0.0f;
            if (w == 0) {
                const float4* wk = reinterpret_cast<const float4*>(W2 + lane * 128);
                const float4* xv4 = reinterpret_cast<const float4*>(sh_x);
                float a0 = b2[lane], a1 = 0.f, a2 = 0.f, a3 = 0.f;
#pragma unroll
                for (int j = 0; j < 32; j++) {
                    float4 xv = xv4[j];
                    float4 wa = wk[j];
                    a0 = fmaf(xv.x, wa.x, a0); a1 = fmaf(xv.y, wa.y, a1);
                    a2 = fmaf(xv.z, wa.z, a2); a3 = fmaf(xv.w, wa.w, a3);
                }
                lg = (a0 + a1) + (a2 + a3);
            } else if (w == 1) {
                const float4* wk = reinterpret_cast<const float4*>(W3 + lane * 128);
                const float4* xv4 = reinterpret_cast<const float4*>(sh_x);
                float a0 = b3[lane], a1 = 0.f, a2 = 0.f, a3 = 0.f;
#pragma unroll
                for (int j = 0; j < 32; j++) {
                    float4 xv = xv4[j];
                    float4 wa = wk[j];
                    a0 = fmaf(xv.x, wa.x, a0); a1 = fmaf(xv.y, wa.y, a1);
                    a2 = fmaf(xv.z, wa.z, a2); a3 = fmaf(xv.w, wa.w, a3);
                }
                float gl = (a0 + a1) + (a2 + a3);
                sh_gl[lane] = 1.0f / (1.0f + expf(-gl));
            } else {
                const float* wk = W4 + lane * (3 * DK_) + 2 * DK_;
                float a0 = b4[lane], a1 = 0.f;
#pragma unroll
                for (int j = 0; j < DK_; j += 2) {
                    a0 = fmaf(sh_x[DK_ + j],     wk[j],     a0);
                    a1 = fmaf(sh_x[DK_ + j + 1], wk[j + 1], a1);
                }
                sh_cB[lane] = a0 + a1;
            }
            asm volatile("bar.sync 7, 96;" ::: "memory");

            if (w == 0) {
                lg = tanhf(lg);
                float LG = sh_gl[lane] * (lg + 1.0f) * 0.5f;
                sh_LG[lane] = LG;
                __syncwarp();
                const float* w4l = W4 + lane * (3 * DK_) + DK_;
                float c0 = sh_cB[lane], c1 = 0.f;
#pragma unroll
                for (int j = 0; j < DK_; j += 2) {
                    c0 = fmaf(sh_LG[j],     w4l[j],     c0);
                    c1 = fmaf(sh_LG[j + 1], w4l[j + 1], c1);
                }
                sh_c[lane] = c0 + c1;
            }
        } else if (w == 3 && bx == 0 && t > 0) {
            // y_{t-1} -> pred[b][t]
            const float* ee = E_e + e_t * DK_;
            const float* ht = g_ht + (t * B_ + b) * DK_;
            const float* w5k = W5 + lane * (2 * DK_);
            float z = b5[lane];
#pragma unroll
            for (int j = 0; j < DK_; j++) {
                z = fmaf(ee[j], w5k[j], z);
                z = fmaf(ht[j], w5k[DK_ + j], z);
            }
            float s = 1.0f / (1.0f + expf(-z));
#pragma unroll
            for (int off = 16; off; off >>= 1)
                s += __shfl_xor_sync(0xffffffffu, s, off);
            if (lane == 0) pred[b * S_ + t] = s * (1.0f / DK_);
        }
        __syncthreads();

        const float LGk = sh_LG[lane];
        const float ck = sh_c[lane];
        float* htn = g_ht + ((t + 1) * B_ + b) * DK_;
        const int w16 = w * 16;

        for (int c = 0; c < nch; c++) {
            const int u = t * nch + c;
            const int slot = u & 1;
            const unsigned phase = (u >> 1) & 1;
            mbar_wait(mb_full + slot * 8, phase);

            const int rs = rstart + c * CHUNK;
            const int nr = min(NQ1 - rs, CHUNK);
            const int wrows = min(max(nr - w16, 0), 16);
            const float* qep = &sh_qe[slot][qoe + w16];
            const float* qnp = &sh_qn[slot][qon + w16];

#pragma unroll 4
            for (int j = 0; j < wrows; j++) {
                const int row = rs + w16 + j;
                const float* srow = &sh_h[slot][(w16 + j) * DK_];
                const ulonglong2* hp = reinterpret_cast<const ulonglong2*>(srow);
                float hk = srow[lane];
                ull a0 = 0ull, a1 = 0ull, a2 = 0ull, a3 = 0ull;
#pragma unroll
                for (int i = 0; i < 4; i++) {
                    ulonglong2 p0 = hp[2 * i];
                    ulonglong2 p1 = hp[2 * i + 1];
                    a0 = ffma2(p0.x, w2r[4 * i + 0], a0);
                    a1 = ffma2(p0.y, w2r[4 * i + 1], a1);
                    a2 = ffma2(p1.x, w2r[4 * i + 2], a2);
                    a3 = ffma2(p1.y, w2r[4 * i + 3], a3);
                }
                float qe = qep[j];
                float qn = qnp[j];
                ull ssum = fadd2(fadd2(a0, a1), fadd2(a2, a3));
                float lo, hi;
                upk2(ssum, lo, hi);
                float z = lo + hi + ck;
                float ex = __expf(-z);
                float gm = __fdividef(1.0f, 1.0f + ex);
                float hn = fmaf(gm, hk, qe * LGk);
                g_h[((long)b * NQ1 + row) * DK_ + lane] = hn;
                if (qn != 0.0f) atomicAdd(htn + lane, qn * hn);
            }

            // last-finisher election: 8th warp to count out issues the refill
            if (lane == 0) {
                int old = atomicAdd(&sh_cnt[slot], 1);
                if ((old & 7) == 7) {
                    const int un = u + 2;
                    if (un < total_u) ISSUE_U(un)
                }
            }
        }

        // ---- publish: my g_ht[t+1] contributions ----
        __threadfence();
        __syncthreads();
        if (tid == 0 && t < TSTEPS - 1) atomicAdd(&g_flag[b], 1);
    }
#undef ISSUE_U
}

// ---------------------------------------------------------------------------
// Kfinal: y_{S-2} -> pred[:, S-1]
// ---------------------------------------------------------------------------
__global__ void k_final(const int* __restrict__ e_data, const float* __restrict__ E_e,
                        const float* __restrict__ W5, const float* __restrict__ b5,
                        float* __restrict__ pred) {
    int b = blockIdx.x;
    int k = threadIdx.x;
    int tlast = S_ - 1;
    int en = e_data[b * S_ + tlast];
    const float* ee = E_e + en * DK_;
    const float* ht = g_ht + (tlast * B_ + b) * DK_;
    const float* w5k = W5 + k * (2 * DK_);
    float z = b5[k];
#pragma unroll
    for (int j = 0; j < DK_; j++) {
        z = fmaf(ee[j], w5k[j], z);
        z = fmaf(ht[j], w5k[DK_ + j], z);
    }
    float s = 1.0f / (1.0f + expf(-z));
#pragma unroll
    for (int off = 16; off; off >>= 1)
        s += __shfl_xor_sync(0xffffffffu, s, off);
    if (k == 0) pred[b * S_ + tlast] = s * (1.0f / DK_);
}

// ---------------------------------------------------------------------------
extern "C" void kernel_launch(void* const* d_in, const int* in_sizes, int n_in,
                              void* d_out, int out_size) {
    const int*   e_data  = (const int*)d_in[0];
    const int*   at_data = (const int*)d_in[1];
    const int*   it_data = (const int*)d_in[2];
    const float* a_data  = (const float*)d_in[3];
    const float* q       = (const float*)d_in[4];
    const float* E_e     = (const float*)d_in[5];
    const float* E_at    = (const float*)d_in[6];
    const float* E_it    = (const float*)d_in[7];
    const float* W1      = (const float*)d_in[8];
    const float* b1      = (const float*)d_in[9];
    const float* W2      = (const float*)d_in[10];
    const float* b2      = (const float*)d_in[11];
    const float* W3      = (const float*)d_in[12];
    const float* b3      = (const float*)d_in[13];
    const float* W4      = (const float*)d_in[14];
    const float* b4      = (const float*)d_in[15];
    const float* W5      = (const float*)d_in[16];
    const float* b5      = (const float*)d_in[17];
    const float* h0      = (const float*)d_in[18];
    float* pred = (float*)d_out;

    k_init<<<2048, 256>>>(h0, pred);
    k_embed<<<(S_ * B_ * DK_ + 255) / 256, 256>>>(e_data, at_data, it_data, a_data,
                                                  E_e, E_at, E_it, W1, b1);
    k_ht0<<<B_, 256>>>(e_data, q, h0);

    k_seq<<<dim3(GX, B_), 256>>>(e_data, q, E_e, W2, b2, W3, b3, W4, b4, W5, b5, pred);

    k_final<<<B_, 32>>>(e_data, E_e, W5, b5, pred);
}

// round 12
// speedup vs baseline: 1.1444x; 1.1444x over previous
#include <cuda_runtime.h>

#define B_      64
#define S_      200
#define DK_     32
#define NQ1     4097
#define CHUNK   128
#define TSTEPS  199
#define NBLK    444           // 148 SMs x 3 CTAs exactly

// Persistent device state (no allocations allowed in kernel_launch).
static __device__ float g_h[(B_ * NQ1 + CHUNK) * DK_];
static __device__ float g_ht[S_ * B_ * DK_];
static __device__ float g_learn[S_ * B_ * DK_];
static __device__ float g_it[S_ * B_ * DK_];
static __device__ int   g_flag[B_];

typedef unsigned long long ull;

__device__ __forceinline__ ull ffma2(ull a, ull b, ull c) {
    ull d;
    asm("fma.rn.f32x2 %0, %1, %2, %3;" : "=l"(d) : "l"(a), "l"(b), "l"(c));
    return d;
}
__device__ __forceinline__ ull fadd2(ull a, ull b) {
    ull d;
    asm("add.rn.f32x2 %0, %1, %2;" : "=l"(d) : "l"(a), "l"(b));
    return d;
}
__device__ __forceinline__ void upk2(ull v, float& lo, float& hi) {
    asm("mov.b64 {%0,%1}, %2;" : "=f"(lo), "=f"(hi) : "l"(v));
}
__device__ __forceinline__ unsigned smem_u32(const void* p) {
    unsigned a;
    asm("{ .reg .u64 t; cvta.to.shared.u64 t, %1; cvt.u32.u64 %0, t; }" : "=r"(a) : "l"(p));
    return a;
}
__device__ __forceinline__ void bulk_g2s(unsigned sdst, const void* gsrc, unsigned bytes,
                                         unsigned mbar) {
    asm volatile(
        "cp.async.bulk.shared::cta.global.mbarrier::complete_tx::bytes [%0], [%1], %2, [%3];"
        :: "r"(sdst), "l"(gsrc), "r"(bytes), "r"(mbar) : "memory");
}
__device__ __forceinline__ void mbar_wait(unsigned mbar, unsigned phase) {
    asm volatile(
        "{\n\t.reg .pred P;\n\t"
        "W_%=:\n\t"
        "mbarrier.try_wait.parity.shared.b64 P, [%0], %1, 0x989680;\n\t"
        "@P bra D_%=;\n\t"
        "bra.uni W_%=;\n\t"
        "D_%=:\n\t}"
        :: "r"(mbar), "r"(phase) : "memory");
}

// ---------------------------------------------------------------------------
__global__ void k_init(const float* __restrict__ h0, float* __restrict__ pred) {
    int stride = gridDim.x * blockDim.x;
    int gid = blockIdx.x * blockDim.x + threadIdx.x;
    for (int i = gid; i < B_ * NQ1 * DK_; i += stride) {
        int nk = i % (NQ1 * DK_);
        g_h[i] = h0[nk];
    }
    for (int i = gid; i < S_ * B_ * DK_; i += stride) g_ht[i] = 0.0f;
    if (gid < B_) { pred[gid * S_] = 0.0f; g_flag[gid] = 0; }
}

// ---------------------------------------------------------------------------
__global__ void k_embed(const int* __restrict__ e_data, const int* __restrict__ at_data,
                        const int* __restrict__ it_data, const float* __restrict__ a_data,
                        const float* __restrict__ E_e, const float* __restrict__ E_at,
                        const float* __restrict__ E_it,
                        const float* __restrict__ W1, const float* __restrict__ b1) {
    int idx = blockIdx.x * blockDim.x + threadIdx.x;
    if (idx >= S_ * B_ * DK_) return;
    int t = idx / (B_ * DK_);
    int rem = idx - t * (B_ * DK_);
    int b = rem >> 5;
    int k = rem & 31;
    int e  = e_data[b * S_ + t];
    int at = at_data[b * S_ + t];
    int it = it_data[b * S_ + t];
    float a = a_data[b * S_ + t];
    const float* ee  = E_e  + e  * DK_;
    const float* eat = E_at + at * DK_;
    const float* w1k = W1 + k * (3 * DK_);
    float s = b1[k];
    float ws = 0.0f;
#pragma unroll
    for (int j = 0; j < DK_; j++) {
        s = fmaf(ee[j],  w1k[j],       s);
        s = fmaf(eat[j], w1k[DK_ + j], s);
        ws += w1k[2 * DK_ + j];
    }
    s = fmaf(a, ws, s);
    g_learn[(t * B_ + b) * DK_ + k] = s;
    g_it[(t * B_ + b) * DK_ + k]    = E_it[it * DK_ + k];
}

// ---------------------------------------------------------------------------
__global__ void k_ht0(const int* __restrict__ e_data, const float* __restrict__ q,
                      const float* __restrict__ h0) {
    int b = blockIdx.x;
    int w = threadIdx.x >> 5;
    int lane = threadIdx.x & 31;
    const float* qr = q + (long)e_data[b * S_] * NQ1;
    float acc = 0.0f;
    for (int n = w; n < NQ1; n += 8) {
        float qv = qr[n];
        if (qv != 0.0f) acc = fmaf(qv, h0[n * DK_ + lane], acc);
    }
    atomicAdd(&g_ht[b * DK_ + lane], acc);
}

// ---------------------------------------------------------------------------
// k_seq: persistent, 444 blocks = 148 SMs x 3 exactly. Batches 0-59 get 7
// blocks, 60-63 get 6; each block owns an equal row slice. 2-slot bulk-TMA
// ring, last-finisher refill election, per-batch step gating.
// ---------------------------------------------------------------------------
__global__ void __launch_bounds__(256, 3)
k_seq(const int* __restrict__ e_data, const float* __restrict__ q,
      const float* __restrict__ E_e,
      const float* __restrict__ W2, const float* __restrict__ b2,
      const float* __restrict__ W3, const float* __restrict__ b3,
      const float* __restrict__ W4, const float* __restrict__ b4,
      const float* __restrict__ W5, const float* __restrict__ b5,
      float* __restrict__ pred) {
    __shared__ __align__(16) float sh_h[2][CHUNK * DK_];   // 32 KB
    __shared__ __align__(16) float sh_qe[2][136];
    __shared__ __align__(16) float sh_qn[2][136];
    __shared__ __align__(8)  ull   sh_mbar[2];
    __shared__ int   sh_cnt[2];
    __shared__ float sh_x[4 * DK_];
    __shared__ float sh_LG[DK_];
    __shared__ float sh_c[DK_];
    __shared__ float sh_gl[DK_];
    __shared__ float sh_cB[DK_];

    const int g = blockIdx.x;
    const int tid = threadIdx.x;
    const int w = tid >> 5;
    const int lane = tid & 31;

    int b, ib, nb;
    if (g < 420) { b = g / 7; ib = g - b * 7; nb = 7; }
    else { int h2 = g - 420; int bb = h2 / 6; b = 60 + bb; ib = h2 - bb * 6; nb = 6; }
    const int rlo = (int)((long)ib * NQ1 / nb);
    const int rhi = (int)((long)(ib + 1) * NQ1 / nb);
    const int nrows = rhi - rlo;
    const int nch = (nrows + CHUNK - 1) >> 7;
    const int total_u = TSTEPS * nch;

    const unsigned mb_full = smem_u32(&sh_mbar[0]);

    if (tid == 0) {
#pragma unroll
        for (int s = 0; s < 2; s++) {
            asm volatile("mbarrier.init.shared.b64 [%0], 1;" :: "r"(mb_full + s * 8));
            sh_cnt[s] = 0;
        }
        asm volatile("fence.proxy.async.shared::cta;" ::: "memory");
    }
    __syncthreads();

#define ISSUE_U(U)                                                                      \
    {                                                                                   \
        int tu = (U) / nch;                                                             \
        int cu = (U) - tu * nch;                                                        \
        int rs_ = rlo + cu * CHUNK;                                                     \
        int cr_ = min(CHUNK, rhi - rs_);                                                \
        int sl_ = (U) & 1;                                                              \
        unsigned mb = mb_full + sl_ * 8;                                                \
        int etu = e_data[b * S_ + tu];                                                  \
        int enu = e_data[b * S_ + tu + 1];                                              \
        ull pe = (ull)(q + (long)etu * NQ1 + rs_);                                      \
        ull pn = (ull)(q + (long)enu * NQ1 + rs_);                                      \
        unsigned qeb = ((cr_ * 4 + (unsigned)(pe & 15)) + 15) & ~15u;                   \
        unsigned qnb = ((cr_ * 4 + (unsigned)(pn & 15)) + 15) & ~15u;                   \
        unsigned hb_ = (unsigned)cr_ * 128u;                                            \
        asm volatile("mbarrier.arrive.expect_tx.shared.b64 _, [%0], %1;"                \
                     :: "r"(mb), "r"(hb_ + qeb + qnb) : "memory");                      \
        bulk_g2s(smem_u32(&sh_h[sl_][0]), g_h + ((long)b * NQ1 + rs_) * DK_, hb_, mb);  \
        bulk_g2s(smem_u32(&sh_qe[sl_][0]), (const void*)(pe & ~15ULL), qeb, mb);        \
        bulk_g2s(smem_u32(&sh_qn[sl_][0]), (const void*)(pn & ~15ULL), qnb, mb);        \
    }

    if (tid == 0) { ISSUE_U(0) ISSUE_U(1) }

    // W4h[lane, 0..31] as 16 f32x2 registers — loaded once.
    ull w2r[16];
    {
        const ulonglong2* wp = reinterpret_cast<const ulonglong2*>(W4 + lane * (3 * DK_));
#pragma unroll
        for (int i = 0; i < 8; i++) {
            ulonglong2 p = __ldg(wp + i);
            w2r[2 * i] = p.x;
            w2r[2 * i + 1] = p.y;
        }
    }

    int u = 0;
    for (int t = 0; t < TSTEPS; t++) {
        if (t > 0) {
            if (tid == 0) {
                int need = nb * t;
                int v;
                do {
                    asm volatile("ld.global.acquire.gpu.b32 %0, [%1];"
                                 : "=r"(v) : "l"(&g_flag[b]));
                    if (v >= need) break;
                    __nanosleep(64);
                } while (true);
            }
            __syncthreads();
        }

        const int e_t = e_data[b * S_ + t];
        const int e_n = e_data[b * S_ + t + 1];

        // ---- prologue: warps 0 (lg), 1 (gl), 2 (it-part of c); warp 3 pred ----
        if (w < 3) {
            if (w == 0) {
                sh_x[lane]           = (t == 0) ? 0.0f : g_learn[((t - 1) * B_ + b) * DK_ + lane];
                sh_x[DK_ + lane]     = g_it[(t * B_ + b) * DK_ + lane];
                sh_x[2 * DK_ + lane] = g_learn[(t * B_ + b) * DK_ + lane];
                sh_x[3 * DK_ + lane] = g_ht[(t * B_ + b) * DK_ + lane];
            }
            asm volatile("bar.sync 7, 96;" ::: "memory");
            float lg = 0.0f;
            if (w == 0) {
                const float4* wk = (const float4*)(W2 + lane * 128);
                const float4* xv4 = (const float4*)sh_x;
                float a0 = b2[lane], a1 = 0.f, a2 = 0.f, a3 = 0.f;
#pragma unroll
                for (int j = 0; j < 32; j++) {
                    float4 xv = xv4[j]; float4 wa = wk[j];
                    a0 = fmaf(xv.x, wa.x, a0); a1 = fmaf(xv.y, wa.y, a1);
                    a2 = fmaf(xv.z, wa.z, a2); a3 = fmaf(xv.w, wa.w, a3);
                }
                lg = (a0 + a1) + (a2 + a3);
            } else if (w == 1) {
                const float4* wk = (const float4*)(W3 + lane * 128);
                const float4* xv4 = (const float4*)sh_x;
                float a0 = b3[lane], a1 = 0.f, a2 = 0.f, a3 = 0.f;
#pragma unroll
                for (int j = 0; j < 32; j++) {
                    float4 xv = xv4[j]; float4 wa = wk[j];
                    a0 = fmaf(xv.x, wa.x, a0); a1 = fmaf(xv.y, wa.y, a1);
                    a2 = fmaf(xv.z, wa.z, a2); a3 = fmaf(xv.w, wa.w, a3);
                }
                float gl = (a0 + a1) + (a2 + a3);
                sh_gl[lane] = 1.0f / (1.0f + expf(-gl));
            } else {
                const float* wk = W4 + lane * (3 * DK_) + 2 * DK_;
                float a0 = b4[lane], a1 = 0.f;
#pragma unroll
                for (int j = 0; j < DK_; j += 2) {
                    a0 = fmaf(sh_x[DK_ + j],     wk[j],     a0);
                    a1 = fmaf(sh_x[DK_ + j + 1], wk[j + 1], a1);
                }
                sh_cB[lane] = a0 + a1;
            }
            asm volatile("bar.sync 7, 96;" ::: "memory");
            if (w == 0) {
                lg = tanhf(lg);
                sh_LG[lane] = sh_gl[lane] * (lg + 1.0f) * 0.5f;
                __syncwarp();
                const float* w4l = W4 + lane * (3 * DK_) + DK_;
                float c0 = sh_cB[lane], c1 = 0.f;
#pragma unroll
                for (int j = 0; j < DK_; j += 2) {
                    c0 = fmaf(sh_LG[j],     w4l[j],     c0);
                    c1 = fmaf(sh_LG[j + 1], w4l[j + 1], c1);
                }
                sh_c[lane] = c0 + c1;
            }
        } else if (w == 3 && ib == 0 && t > 0) {
            const float* ee = E_e + e_t * DK_;
            const float* ht = g_ht + (t * B_ + b) * DK_;
            const float* w5k = W5 + lane * (2 * DK_);
            float z = b5[lane];
#pragma unroll
            for (int j = 0; j < DK_; j++) {
                z = fmaf(ee[j], w5k[j], z);
                z = fmaf(ht[j], w5k[DK_ + j], z);
            }
            float s = 1.0f / (1.0f + expf(-z));
#pragma unroll
            for (int off = 16; off; off >>= 1)
                s += __shfl_xor_sync(0xffffffffu, s, off);
            if (lane == 0) pred[b * S_ + t] = s * (1.0f / DK_);
        }
        __syncthreads();

        const float LGk = sh_LG[lane];
        const float ck = sh_c[lane];
        float* htn = g_ht + ((t + 1) * B_ + b) * DK_;
        const int w16 = w * 16;

        for (int c = 0; c < nch; c++, u++) {
            const int slot = u & 1;
            const unsigned phase = (u >> 1) & 1;
            mbar_wait(mb_full + slot * 8, phase);

            const int rs = rlo + c * CHUNK;
            const int cr = min(CHUNK, rhi - rs);
            const int wrows = min(max(cr - w16, 0), 16);
            const int qoe = (int)(((ull)(q + (long)e_t * NQ1 + rs) >> 2) & 3);
            const int qon = (int)(((ull)(q + (long)e_n * NQ1 + rs) >> 2) & 3);
            const float* qep = &sh_qe[slot][qoe + w16];
            const float* qnp = &sh_qn[slot][qon + w16];
            const float* srow = &sh_h[slot][w16 * DK_];
            float* gp = g_h + ((long)b * NQ1 + rs + w16) * DK_ + lane;

#define ROW_BODY                                                               \
    {                                                                          \
        const ulonglong2* hp = reinterpret_cast<const ulonglong2*>(srow);      \
        float hk = srow[lane];                                                 \
        ull a0 = 0ull, a1 = 0ull, a2 = 0ull, a3 = 0ull;                        \
        _Pragma("unroll")                                                      \
        for (int i = 0; i < 4; i++) {                                          \
            ulonglong2 p0 = hp[2 * i];                                         \
            ulonglong2 p1 = hp[2 * i + 1];                                     \
            a0 = ffma2(p0.x, w2r[4 * i + 0], a0);                              \
            a1 = ffma2(p0.y, w2r[4 * i + 1], a1);                              \
            a2 = ffma2(p1.x, w2r[4 * i + 2], a2);                              \
            a3 = ffma2(p1.y, w2r[4 * i + 3], a3);                              \
        }                                                                      \
        float qe = qep[j];                                                     \
        float qn = qnp[j];                                                     \
        ull ssum = fadd2(fadd2(a0, a1), fadd2(a2, a3));                        \
        float lo, hi;                                                          \
        upk2(ssum, lo, hi);                                                    \
        float z = lo + hi + ck;                                                \
        float gm = __fdividef(1.0f, 1.0f + __expf(-z));                        \
        float hn = fmaf(gm, hk, qe * LGk);                                     \
        *gp = hn;                                                              \
        if (qn != 0.0f) atomicAdd(htn + lane, qn * hn);                        \
        srow += DK_;                                                           \
        gp += DK_;                                                             \
    }

            if (wrows == 16) {
#pragma unroll 4
                for (int j = 0; j < 16; j++) ROW_BODY
            } else {
                for (int j = 0; j < wrows; j++) ROW_BODY
            }
#undef ROW_BODY

            if (lane == 0) {
                int old = atomicAdd(&sh_cnt[slot], 1);
                if ((old & 7) == 7) {
                    const int un = u + 2;
                    if (un < total_u) ISSUE_U(un)
                }
            }
        }

        __threadfence();
        __syncthreads();
        if (tid == 0 && t < TSTEPS - 1) atomicAdd(&g_flag[b], 1);
    }
#undef ISSUE_U
}

// ---------------------------------------------------------------------------
__global__ void k_final(const int* __restrict__ e_data, const float* __restrict__ E_e,
                        const float* __restrict__ W5, const float* __restrict__ b5,
                        float* __restrict__ pred) {
    int b = blockIdx.x;
    int k = threadIdx.x;
    int tlast = S_ - 1;
    int en = e_data[b * S_ + tlast];
    const float* ee = E_e + en * DK_;
    const float* ht = g_ht + (tlast * B_ + b) * DK_;
    const float* w5k = W5 + k * (2 * DK_);
    float z = b5[k];
#pragma unroll
    for (int j = 0; j < DK_; j++) {
        z = fmaf(ee[j], w5k[j], z);
        z = fmaf(ht[j], w5k[DK_ + j], z);
    }
    float s = 1.0f / (1.0f + expf(-z));
#pragma unroll
    for (int off = 16; off; off >>= 1)
        s += __shfl_xor_sync(0xffffffffu, s, off);
    if (k == 0) pred[b * S_ + tlast] = s * (1.0f / DK_);
}

// ---------------------------------------------------------------------------
extern "C" void kernel_launch(void* const* d_in, const int* in_sizes, int n_in,
                              void* d_out, int out_size) {
    const int*   e_data  = (const int*)d_in[0];
    const int*   at_data = (const int*)d_in[1];
    const int*   it_data = (const int*)d_in[2];
    const float* a_data  = (const float*)d_in[3];
    const float* q       = (const float*)d_in[4];
    const float* E_e     = (const float*)d_in[5];
    const float* E_at    = (const float*)d_in[6];
    const float* E_it    = (const float*)d_in[7];
    const float* W1      = (const float*)d_in[8];
    const float* b1      = (const float*)d_in[9];
    const float* W2      = (const float*)d_in[10];
    const float* b2      = (const float*)d_in[11];
    const float* W3      = (const float*)d_in[12];
    const float* b3      = (const float*)d_in[13];
    const float* W4      = (const float*)d_in[14];
    const float* b4      = (const float*)d_in[15];
    const float* W5      = (const float*)d_in[16];
    const float* b5      = (const float*)d_in[17];
    const float* h0      = (const float*)d_in[18];
    float* pred = (float*)d_out;

    k_init<<<2048, 256>>>(h0, pred);
    k_embed<<<(S_ * B_ * DK_ + 255) / 256, 256>>>(e_data, at_data, it_data, a_data,
                                                  E_e, E_at, E_it, W1, b1);
    k_ht0<<<B_, 256>>>(e_data, q, h0);

    k_seq<<<NBLK, 256>>>(e_data, q, E_e, W2, b2, W3, b3, W4, b4, W5, b5, pred);

    k_final<<<B_, 32>>>(e_data, E_e, W5, b5, pred);
}